// round 14
// baseline (speedup 1.0000x reference)
#include <cuda_runtime.h>
#include <cuda_bf16.h>
#include <cstdint>
#include <math.h>

// ---------------- problem constants ----------------
#define BB   128      // batch
#define SS   256      // seq len
#define WW   20       // chars per word
#define WVV  50000
#define CVV  100
#define WEE  300
#define CEE  50
#define CCC  100
#define HIDD 512
#define HH   256      // per-direction hidden
#define DINN 400      // WE + CC
#define TT   12
#define G4H  1024     // 4*H
#define TAG_START 9
#define TAG_STOP  10
#define TAG_PAD   11

// ---------------- packed f32x2 helpers (FFMA2 path, sm_103a) --------------
typedef unsigned long long ull;

__device__ __forceinline__ ull dup2(float x) {
    ull r;
    asm("mov.b64 %0, {%1, %1};" : "=l"(r) : "f"(x));
    return r;
}
__device__ __forceinline__ void ffma2(ull& d, ull a, ull b) {
    asm("fma.rn.f32x2 %0, %1, %2, %0;" : "+l"(d) : "l"(a), "l"(b));
}
__device__ __forceinline__ void unpack2(float& lo, float& hi, ull v) {
    asm("mov.b64 {%0, %1}, %2;" : "=f"(lo), "=f"(hi) : "l"(v));
}

// ---------------- device scratch (static, allocation-free) ----------------
__device__ float g_PT[3 * CVV * CCC];                    // projected char table [k][c][o]
__device__ float g_bias[2 * G4H];                        // b_ih + b_hh per dir
__device__ float g_emb[SS * BB * DINN];                  // [s][b][din]
__device__ float g_xwT[2u * SS * G4H * BB];              // [dir][t][col][b]
__device__ float g_hT [2u * SS * HH  * BB];              // [dir][t][j][b]
__device__ float g_feats[SS * BB * TT];                  // [s][b][tag]
__device__ unsigned char g_bp[SS * BB * TT];             // backpointers
__device__ int   g_bar[2 * SS];                          // per-step barriers

// ---------------- K1: precompute PT, fused biases, zero barriers ----------
__global__ void k_prep(const float* __restrict__ conv_w,
                       const float* __restrict__ char_table,
                       const float* __restrict__ bif, const float* __restrict__ bhf,
                       const float* __restrict__ bib, const float* __restrict__ bhb)
{
    int idx = blockIdx.x * blockDim.x + threadIdx.x;
    if (idx < 3 * CVV * CCC) {
        int o = idx % CCC;
        int c = (idx / CCC) % CVV;
        int k = idx / (CVV * CCC);
        float s = 0.f;
        #pragma unroll 10
        for (int e = 0; e < CEE; e++)
            s += conv_w[(o * CEE + e) * 3 + k] * char_table[c * CEE + e];
        g_PT[k * (CVV * CCC) + c * CCC + o] = s;
    }
    if (idx < G4H)            g_bias[idx]        = bif[idx]        + bhf[idx];
    else if (idx < 2 * G4H)   g_bias[idx]        = bib[idx - G4H]  + bhb[idx - G4H];
    if (idx < 2 * SS)         g_bar[idx] = 0;
}

// ---------------- K2: word gather + char conv/maxpool -> emb [s][b][din] ---
__global__ void k_embed(const int* __restrict__ widx,
                        const int* __restrict__ cidx,
                        const float* __restrict__ wt,
                        const float* __restrict__ cb)
{
    __shared__ int ch[WW];
    int bs  = blockIdx.x;           // 0..B*S-1
    int s   = bs >> 7;
    int b   = bs & 127;
    int tid = threadIdx.x;

    int w = widx[b * SS + s];
    float* dst = g_emb + (size_t)(s * BB + b) * DINN;
    for (int i = tid; i < WEE; i += 128)
        dst[i] = wt[(size_t)w * WEE + i];

    if (tid < WW) ch[tid] = cidx[((size_t)(b * SS + s)) * WW + tid];
    __syncthreads();

    if (tid < CCC) {
        int o = tid;
        float bias = cb[o];
        float m = -1e30f;
        const float* PT0 = g_PT;
        const float* PT1 = g_PT + CVV * CCC;
        const float* PT2 = g_PT + 2 * CVV * CCC;
        #pragma unroll
        for (int t = 0; t < WW; t++) {
            float v = bias + PT1[ch[t] * CCC + o];
            if (t > 0)      v += PT0[ch[t - 1] * CCC + o];
            if (t < WW - 1) v += PT2[ch[t + 1] * CCC + o];
            m = fmaxf(m, v);
        }
        dst[WEE + o] = fmaxf(m, 0.0f);
    }
}

// ---------------- K3: big input GEMM (FFMA2 inner) ------------------------
// C[dir][t][col][b] = sum_k W_ih[dir][col][k] * emb[t][b][k] + bias[dir][col]
// M = 2048 rows (dir x col), N = 32768 (t x b), K = 400.
__global__ void __launch_bounds__(256, 2)
k_gemm(const float* __restrict__ wf, const float* __restrict__ wb)
{
    __shared__ float sA[16][128];
    __shared__ float sB[16][128];

    int nb = blockIdx.x;            // t (one timestep per N-tile)
    int mb = blockIdx.y;            // M tile (128 rows)
    int tid = threadIdx.x;
    int tx = tid & 15, ty = tid >> 4;

    int dir = mb >> 3;
    int r0  = (mb & 7) * 128;
    const float* W    = dir ? wb : wf;
    const float* Brow = g_emb + (size_t)nb * BB * DINN;

    // acc2[i][jp] holds the (j=2*jp, 2*jp+1) pair for output row i
    ull acc2[8][4];
    #pragma unroll
    for (int i = 0; i < 8; i++)
        #pragma unroll
        for (int jp = 0; jp < 4; jp++) acc2[i][jp] = 0ull;

    for (int k0 = 0; k0 < DINN; k0 += 16) {
        #pragma unroll
        for (int it = 0; it < 2; it++) {
            int idx = tid + it * 256;
            int ml = idx >> 2, q = idx & 3;
            float4 va = *(const float4*)(W    + (size_t)(r0 + ml) * DINN + k0 + q * 4);
            sA[q*4+0][ml] = va.x; sA[q*4+1][ml] = va.y;
            sA[q*4+2][ml] = va.z; sA[q*4+3][ml] = va.w;
            float4 vb = *(const float4*)(Brow + (size_t)ml * DINN + k0 + q * 4);
            sB[q*4+0][ml] = vb.x; sB[q*4+1][ml] = vb.y;
            sB[q*4+2][ml] = vb.z; sB[q*4+3][ml] = vb.w;
        }
        __syncthreads();
        #pragma unroll
        for (int k = 0; k < 16; k++) {
            float4 a0 = *(const float4*)&sA[k][ty * 8];
            float4 a1 = *(const float4*)&sA[k][ty * 8 + 4];
            ulonglong2 bA = *(const ulonglong2*)&sB[k][tx * 8];     // pairs j0-1, j2-3
            ulonglong2 bB = *(const ulonglong2*)&sB[k][tx * 8 + 4]; // pairs j4-5, j6-7
            float av[8] = {a0.x,a0.y,a0.z,a0.w,a1.x,a1.y,a1.z,a1.w};
            ull bp0 = bA.x, bp1 = bA.y, bp2 = bB.x, bp3 = bB.y;
            #pragma unroll
            for (int i = 0; i < 8; i++) {
                ull ad = dup2(av[i]);
                ffma2(acc2[i][0], ad, bp0);
                ffma2(acc2[i][1], ad, bp1);
                ffma2(acc2[i][2], ad, bp2);
                ffma2(acc2[i][3], ad, bp3);
            }
        }
        __syncthreads();
    }

    int t = nb;
    #pragma unroll
    for (int i = 0; i < 8; i++) {
        int col = r0 + ty * 8 + i;                 // 0..1023
        float bi = g_bias[dir * G4H + col];
        float r[8];
        unpack2(r[0], r[1], acc2[i][0]);
        unpack2(r[2], r[3], acc2[i][1]);
        unpack2(r[4], r[5], acc2[i][2]);
        unpack2(r[6], r[7], acc2[i][3]);
        float* orow = g_xwT + (((size_t)dir * SS + t) * G4H + col) * BB + tx * 8;
        *(float4*)(orow)     = make_float4(r[0]+bi, r[1]+bi, r[2]+bi, r[3]+bi);
        *(float4*)(orow + 4) = make_float4(r[4]+bi, r[5]+bi, r[6]+bi, r[7]+bi);
    }
}

// ---------------- K4: persistent BiLSTM recurrence (FFMA2, no staging) ----
// 128 blocks (<=148 SMs, wave-1 co-resident). 64 blocks per direction.
// Block owns 4 h-indices (16 gate rows of W_hh resident in SMEM).
// Thread (lane, jl): 4 consecutive b, one j. c-state in registers.
// h_prev read directly via LDG (per-timestep-unique addresses -> no stale L1;
// visibility guaranteed by __threadfence + grid barrier).
__device__ __forceinline__ float sigmoidf_(float x) { return 1.0f / (1.0f + expf(-x)); }

__global__ void __launch_bounds__(128, 1)
k_lstm(const float* __restrict__ whh_f, const float* __restrict__ whh_b)
{
    __shared__ float sw[4][256][4];     // [jl][k][gate]  (16 KB)

    int tid  = threadIdx.x;
    int dir  = blockIdx.x >> 6;
    int ib   = blockIdx.x & 63;
    int j0   = ib * 4;
    int lane = tid & 31;
    int jl   = tid >> 5;
    int b0   = lane * 4;
    int jg   = j0 + jl;

    const float* whh = dir ? whh_b : whh_f;
    for (int idx = tid; idx < 4096; idx += 128) {
        int jj  = idx >> 10;
        int rem = idx & 1023;
        int k   = rem >> 2;
        int g   = rem & 3;
        sw[jj][k][g] = whh[(size_t)((g << 8) + j0 + jj) * HH + k];
    }
    __syncthreads();

    float c[4] = {0.f, 0.f, 0.f, 0.f};
    int* bar = g_bar + dir * SS;

    for (int st = 0; st < SS; st++) {
        int t = dir ? (SS - 1 - st) : st;

        // prefetch x-projection (independent of h_prev) early
        const float* xr = g_xwT + (((size_t)dir * SS + t) * G4H + jg) * BB + b0;
        float4 xi = *(const float4*)(xr);
        float4 xf = *(const float4*)(xr + 256 * BB);
        float4 xg = *(const float4*)(xr + 512 * BB);
        float4 xo = *(const float4*)(xr + 768 * BB);

        // packed accumulators: [gate][b-pair]
        ull ai0 = 0ull, ai1 = 0ull;
        ull af0 = 0ull, af1 = 0ull;
        ull ag0 = 0ull, ag1 = 0ull;
        ull ao0 = 0ull, ao1 = 0ull;

        if (st > 0) {
            int tp = dir ? (t + 1) : (t - 1);
            const float* hp = g_hT + ((size_t)(dir * SS + tp) * HH) * BB + b0;
            const float4* wrow = (const float4*)&sw[jl][0][0];
            #pragma unroll 8
            for (int k = 0; k < HH; k++) {
                ulonglong2 h2 = *(const ulonglong2*)(hp + (size_t)k * BB); // b pairs
                float4 w4 = wrow[k];                                        // broadcast LDS
                ull wi = dup2(w4.x), wfv = dup2(w4.y);
                ull wg = dup2(w4.z), wov = dup2(w4.w);
                ffma2(ai0, wi,  h2.x); ffma2(ai1, wi,  h2.y);
                ffma2(af0, wfv, h2.x); ffma2(af1, wfv, h2.y);
                ffma2(ag0, wg,  h2.x); ffma2(ag1, wg,  h2.y);
                ffma2(ao0, wov, h2.x); ffma2(ao1, wov, h2.y);
            }
        }

        float ia[4], fa[4], ga[4], oa[4];
        unpack2(ia[0], ia[1], ai0); unpack2(ia[2], ia[3], ai1);
        unpack2(fa[0], fa[1], af0); unpack2(fa[2], fa[3], af1);
        unpack2(ga[0], ga[1], ag0); unpack2(ga[2], ga[3], ag1);
        unpack2(oa[0], oa[1], ao0); unpack2(oa[2], oa[3], ao1);

        float xiv[4] = {xi.x, xi.y, xi.z, xi.w};
        float xfv[4] = {xf.x, xf.y, xf.z, xf.w};
        float xgv[4] = {xg.x, xg.y, xg.z, xg.w};
        float xov[4] = {xo.x, xo.y, xo.z, xo.w};

        float hv[4];
        #pragma unroll
        for (int bb = 0; bb < 4; bb++) {
            float ig = sigmoidf_(ia[bb] + xiv[bb]);
            float fg = sigmoidf_(fa[bb] + xfv[bb]);
            float gg = tanhf(ga[bb] + xgv[bb]);
            float og = sigmoidf_(oa[bb] + xov[bb]);
            c[bb] = fg * c[bb] + ig * gg;
            hv[bb] = og * tanhf(c[bb]);
        }
        *(float4*)(g_hT + (((size_t)dir * SS + t) * HH + jg) * BB + b0) =
            make_float4(hv[0], hv[1], hv[2], hv[3]);

        if (st < SS - 1) {
            __threadfence();
            __syncthreads();
            if (tid == 0) {
                atomicAdd(&bar[st], 1);
                while (((volatile int*)bar)[st] < 64) { }
            }
            __syncthreads();
        }
    }
}

// ---------------- K5: feats = lstm_out @ h2t_w^T + h2t_b ------------------
__global__ void k_feats(const float* __restrict__ h2t_w, const float* __restrict__ h2t_b)
{
    __shared__ float sw[TT * HIDD];      // 24 KB
    int t = blockIdx.x;
    int b = threadIdx.x;
    for (int i = b; i < TT * HIDD; i += 128) sw[i] = h2t_w[i];
    __syncthreads();

    float acc[TT];
    #pragma unroll
    for (int tg = 0; tg < TT; tg++) acc[tg] = h2t_b[tg];

    const float* hf = g_hT + ((size_t)(0 * SS + t) * HH) * BB + b;
    const float* hb = g_hT + ((size_t)(1 * SS + t) * HH) * BB + b;
    for (int j = 0; j < HH; j++) {
        float vf = hf[(size_t)j * BB];
        float vb = hb[(size_t)j * BB];
        #pragma unroll
        for (int tg = 0; tg < TT; tg++)
            acc[tg] += vf * sw[tg * HIDD + j] + vb * sw[tg * HIDD + HH + j];
    }
    float* dst = g_feats + (size_t)(t * BB + b) * TT;
    #pragma unroll
    for (int tg = 0; tg < TT; tg++) dst[tg] = acc[tg];
}

// ---------------- K6: Viterbi + backtrace ---------------------------------
// 16 blocks x (8 batch x 12 tags) threads.
__global__ void k_viterbi(const float* __restrict__ trans,
                          const int* __restrict__ mask,
                          float* __restrict__ out)
{
    __shared__ float str[TT * TT];
    __shared__ float alpha[8][TT];
    __shared__ float fin[8][TT];

    int tid = threadIdx.x;       // 0..95
    int bl = tid / TT;
    int nx = tid % TT;
    int b  = blockIdx.x * 8 + bl;

    for (int i = tid; i < TT * TT; i += 96) str[i] = trans[i];
    alpha[bl][nx] = (nx == TAG_START) ? 0.0f : -10000.0f;
    __syncthreads();

    for (int s = 0; s < SS; s++) {
        float f = g_feats[((size_t)(s * BB) + b) * TT + nx];
        float bestv = -3.4e38f; int bestp = 0;
        #pragma unroll
        for (int p = 0; p < TT; p++) {
            float v = (alpha[bl][p] + str[p * TT + nx]) + f;
            if (v > bestv) { bestv = v; bestp = p; }
        }
        g_bp[((size_t)(s * BB) + b) * TT + nx] = (unsigned char)bestp;
        int valid = mask[b * SS + s];
        float cur = alpha[bl][nx];
        __syncthreads();
        alpha[bl][nx] = valid ? bestv : cur;
        __syncthreads();
    }

    fin[bl][nx] = alpha[bl][nx] + str[TAG_STOP * TT + nx];
    __syncthreads();

    if (nx == 0) {
        float bv = fin[bl][0]; int bt = 0;
        #pragma unroll
        for (int p = 1; p < TT; p++)
            if (fin[bl][p] > bv) { bv = fin[bl][p]; bt = p; }
        out[b] = bv;

        int len = 0;
        for (int s = 0; s < SS; s++) len += mask[b * SS + s];

        int tag = bt;
        for (int s = SS - 1; s >= 0; s--) {
            if (s < len) {
                out[BB + b * SS + s] = (float)tag;
                tag = g_bp[((size_t)(s * BB) + b) * TT + tag];
            } else {
                out[BB + b * SS + s] = (float)TAG_PAD;
            }
        }
    }
}

// ---------------- launch ---------------------------------------------------
extern "C" void kernel_launch(void* const* d_in, const int* in_sizes, int n_in,
                              void* d_out, int out_size)
{
    (void)in_sizes; (void)n_in; (void)out_size;
    const int*   word_idxs  = (const int*)  d_in[0];
    const int*   char_idxs  = (const int*)  d_in[1];
    const int*   mask       = (const int*)  d_in[2];
    const float* word_table = (const float*)d_in[3];
    const float* char_table = (const float*)d_in[4];
    const float* conv_w     = (const float*)d_in[5];
    const float* conv_b     = (const float*)d_in[6];
    const float* w_ih_f     = (const float*)d_in[7];
    const float* w_hh_f     = (const float*)d_in[8];
    const float* b_ih_f     = (const float*)d_in[9];
    const float* b_hh_f     = (const float*)d_in[10];
    const float* w_ih_b     = (const float*)d_in[11];
    const float* w_hh_b     = (const float*)d_in[12];
    const float* b_ih_b     = (const float*)d_in[13];
    const float* b_hh_b     = (const float*)d_in[14];
    const float* h2t_w      = (const float*)d_in[15];
    const float* h2t_b      = (const float*)d_in[16];
    const float* trans      = (const float*)d_in[17];
    float* out = (float*)d_out;

    k_prep<<<(3 * CVV * CCC + 255) / 256, 256>>>(conv_w, char_table,
                                                 b_ih_f, b_hh_f, b_ih_b, b_hh_b);
    k_embed<<<BB * SS, 128>>>(word_idxs, char_idxs, word_table, conv_b);
    k_gemm<<<dim3(SS, 16), 256>>>(w_ih_f, w_ih_b);
    k_lstm<<<128, 128>>>(w_hh_f, w_hh_b);
    k_feats<<<SS, 128>>>(h2t_w, h2t_b);
    k_viterbi<<<16, 96>>>(trans, mask, out);
}

// round 15
// speedup vs baseline: 1.0919x; 1.0919x over previous
#include <cuda_runtime.h>
#include <cuda_bf16.h>
#include <cstdint>
#include <math.h>

// ---------------- problem constants ----------------
#define BB   128      // batch
#define SS   256      // seq len
#define WW   20       // chars per word
#define WVV  50000
#define CVV  100
#define WEE  300
#define CEE  50
#define CCC  100
#define HIDD 512
#define HH   256      // per-direction hidden
#define DINN 400      // WE + CC
#define TT   12
#define G4H  1024     // 4*H
#define TAG_START 9
#define TAG_STOP  10
#define TAG_PAD   11

// ---------------- packed f32x2 helpers (FFMA2 path, sm_103a) --------------
typedef unsigned long long ull;

__device__ __forceinline__ ull dup2(float x) {
    ull r;
    asm("mov.b64 %0, {%1, %1};" : "=l"(r) : "f"(x));
    return r;
}
__device__ __forceinline__ void ffma2(ull& d, ull a, ull b) {
    asm("fma.rn.f32x2 %0, %1, %2, %0;" : "+l"(d) : "l"(a), "l"(b));
}
__device__ __forceinline__ void unpack2(float& lo, float& hi, ull v) {
    asm("mov.b64 {%0, %1}, %2;" : "=f"(lo), "=f"(hi) : "l"(v));
}

// ---------------- device scratch (static, allocation-free) ----------------
__device__ float g_PT[3 * CVV * CCC];                    // projected char table [k][c][o]
__device__ float g_bias[2 * G4H];                        // b_ih + b_hh per dir
__device__ float g_emb[SS * BB * DINN];                  // [s][b][din]
__device__ float g_xwT[2u * SS * G4H * BB];              // [dir][t][col][b]
__device__ float g_hT [2u * SS * HH  * BB];              // [dir][t][j][b]
__device__ float g_feats[SS * BB * TT];                  // [s][b][tag]
__device__ unsigned char g_bp[SS * BB * TT];             // backpointers
__device__ int   g_bar[2 * SS];                          // per-step barriers

// ---------------- K1: precompute PT, fused biases, zero barriers ----------
__global__ void k_prep(const float* __restrict__ conv_w,
                       const float* __restrict__ char_table,
                       const float* __restrict__ bif, const float* __restrict__ bhf,
                       const float* __restrict__ bib, const float* __restrict__ bhb)
{
    int idx = blockIdx.x * blockDim.x + threadIdx.x;
    if (idx < 3 * CVV * CCC) {
        int o = idx % CCC;
        int c = (idx / CCC) % CVV;
        int k = idx / (CVV * CCC);
        float s = 0.f;
        #pragma unroll 10
        for (int e = 0; e < CEE; e++)
            s += conv_w[(o * CEE + e) * 3 + k] * char_table[c * CEE + e];
        g_PT[k * (CVV * CCC) + c * CCC + o] = s;
    }
    if (idx < G4H)            g_bias[idx]        = bif[idx]        + bhf[idx];
    else if (idx < 2 * G4H)   g_bias[idx]        = bib[idx - G4H]  + bhb[idx - G4H];
    if (idx < 2 * SS)         g_bar[idx] = 0;
}

// ---------------- K2: word gather + char conv/maxpool -> emb [s][b][din] ---
__global__ void k_embed(const int* __restrict__ widx,
                        const int* __restrict__ cidx,
                        const float* __restrict__ wt,
                        const float* __restrict__ cb)
{
    __shared__ int ch[WW];
    int bs  = blockIdx.x;           // 0..B*S-1
    int s   = bs >> 7;
    int b   = bs & 127;
    int tid = threadIdx.x;

    int w = widx[b * SS + s];
    float* dst = g_emb + (size_t)(s * BB + b) * DINN;
    for (int i = tid; i < WEE; i += 128)
        dst[i] = wt[(size_t)w * WEE + i];

    if (tid < WW) ch[tid] = cidx[((size_t)(b * SS + s)) * WW + tid];
    __syncthreads();

    if (tid < CCC) {
        int o = tid;
        float bias = cb[o];
        float m = -1e30f;
        const float* PT0 = g_PT;
        const float* PT1 = g_PT + CVV * CCC;
        const float* PT2 = g_PT + 2 * CVV * CCC;
        #pragma unroll
        for (int t = 0; t < WW; t++) {
            float v = bias + PT1[ch[t] * CCC + o];
            if (t > 0)      v += PT0[ch[t - 1] * CCC + o];
            if (t < WW - 1) v += PT2[ch[t + 1] * CCC + o];
            m = fmaxf(m, v);
        }
        dst[WEE + o] = fmaxf(m, 0.0f);
    }
}

// ---------------- K3: big input GEMM (FFMA2 inner, staged SMEM) -----------
// C[dir][t][col][b] = sum_k W_ih[dir][col][k] * emb[t][b][k] + bias[dir][col]
// M = 2048 rows (dir x col), N = 32768 (t x b), K = 400.
__global__ void __launch_bounds__(256, 2)
k_gemm(const float* __restrict__ wf, const float* __restrict__ wb)
{
    __shared__ float sA[16][128];
    __shared__ float sB[16][128];

    int nb = blockIdx.x;            // t (one timestep per N-tile)
    int mb = blockIdx.y;            // M tile (128 rows)
    int tid = threadIdx.x;
    int tx = tid & 15, ty = tid >> 4;

    int dir = mb >> 3;
    int r0  = (mb & 7) * 128;
    const float* W    = dir ? wb : wf;
    const float* Brow = g_emb + (size_t)nb * BB * DINN;

    // acc2[i][jp] holds the (j=2*jp, 2*jp+1) pair for output row i
    ull acc2[8][4];
    #pragma unroll
    for (int i = 0; i < 8; i++)
        #pragma unroll
        for (int jp = 0; jp < 4; jp++) acc2[i][jp] = 0ull;

    for (int k0 = 0; k0 < DINN; k0 += 16) {
        #pragma unroll
        for (int it = 0; it < 2; it++) {
            int idx = tid + it * 256;
            int ml = idx >> 2, q = idx & 3;
            float4 va = *(const float4*)(W    + (size_t)(r0 + ml) * DINN + k0 + q * 4);
            sA[q*4+0][ml] = va.x; sA[q*4+1][ml] = va.y;
            sA[q*4+2][ml] = va.z; sA[q*4+3][ml] = va.w;
            float4 vb = *(const float4*)(Brow + (size_t)ml * DINN + k0 + q * 4);
            sB[q*4+0][ml] = vb.x; sB[q*4+1][ml] = vb.y;
            sB[q*4+2][ml] = vb.z; sB[q*4+3][ml] = vb.w;
        }
        __syncthreads();
        #pragma unroll
        for (int k = 0; k < 16; k++) {
            float4 a0 = *(const float4*)&sA[k][ty * 8];
            float4 a1 = *(const float4*)&sA[k][ty * 8 + 4];
            ulonglong2 bA = *(const ulonglong2*)&sB[k][tx * 8];     // pairs j0-1, j2-3
            ulonglong2 bB = *(const ulonglong2*)&sB[k][tx * 8 + 4]; // pairs j4-5, j6-7
            float av[8] = {a0.x,a0.y,a0.z,a0.w,a1.x,a1.y,a1.z,a1.w};
            ull bp0 = bA.x, bp1 = bA.y, bp2 = bB.x, bp3 = bB.y;
            #pragma unroll
            for (int i = 0; i < 8; i++) {
                ull ad = dup2(av[i]);
                ffma2(acc2[i][0], ad, bp0);
                ffma2(acc2[i][1], ad, bp1);
                ffma2(acc2[i][2], ad, bp2);
                ffma2(acc2[i][3], ad, bp3);
            }
        }
        __syncthreads();
    }

    int t = nb;
    #pragma unroll
    for (int i = 0; i < 8; i++) {
        int col = r0 + ty * 8 + i;                 // 0..1023
        float bi = g_bias[dir * G4H + col];
        float r[8];
        unpack2(r[0], r[1], acc2[i][0]);
        unpack2(r[2], r[3], acc2[i][1]);
        unpack2(r[4], r[5], acc2[i][2]);
        unpack2(r[6], r[7], acc2[i][3]);
        float* orow = g_xwT + (((size_t)dir * SS + t) * G4H + col) * BB + tx * 8;
        *(float4*)(orow)     = make_float4(r[0]+bi, r[1]+bi, r[2]+bi, r[3]+bi);
        *(float4*)(orow + 4) = make_float4(r[4]+bi, r[5]+bi, r[6]+bi, r[7]+bi);
    }
}

// ---------------- K4: persistent BiLSTM recurrence ------------------------
// R12 structure (staged SMEM h-pipeline, nanosleep spin) + FFMA2 inner math.
// 128 blocks (<=148 SMs, wave-1 co-resident). 64 blocks per direction.
// Block owns 4 h-indices (16 gate rows of W_hh resident in SMEM).
// Thread (lane, jl): 4 consecutive b, one j. c-state in registers.
__device__ __forceinline__ float sigmoidf_(float x) { return 1.0f / (1.0f + expf(-x)); }

__global__ void __launch_bounds__(128, 1)
k_lstm(const float* __restrict__ whh_f, const float* __restrict__ whh_b)
{
    __shared__ float sw[4][256][4];     // [jl][k][gate]  (16 KB)
    __shared__ float sh[32][132];       // [k-chunk][b]   (16.9 KB)

    int tid  = threadIdx.x;
    int dir  = blockIdx.x >> 6;
    int ib   = blockIdx.x & 63;
    int j0   = ib * 4;
    int lane = tid & 31;
    int jl   = tid >> 5;
    int b0   = lane * 4;
    int jg   = j0 + jl;

    const float* whh = dir ? whh_b : whh_f;
    for (int idx = tid; idx < 4096; idx += 128) {
        int jj  = idx >> 10;
        int rem = idx & 1023;
        int k   = rem >> 2;
        int g   = rem & 3;
        sw[jj][k][g] = whh[(size_t)((g << 8) + j0 + jj) * HH + k];
    }
    __syncthreads();

    float c[4] = {0.f, 0.f, 0.f, 0.f};
    int* bar = g_bar + dir * SS;

    for (int st = 0; st < SS; st++) {
        int t = dir ? (SS - 1 - st) : st;

        // packed accumulators: [gate][b-pair]
        ull ai0 = 0ull, ai1 = 0ull;
        ull af0 = 0ull, af1 = 0ull;
        ull ag0 = 0ull, ag1 = 0ull;
        ull ao0 = 0ull, ao1 = 0ull;

        if (st > 0) {
            int tp = dir ? (t + 1) : (t - 1);
            const float* hsrc = g_hT + ((size_t)(dir * SS + tp) * HH) * BB;
            for (int kb = 0; kb < 8; kb++) {
                #pragma unroll
                for (int ph = 0; ph < 8; ph++) {
                    int kk = ph * 4 + jl;
                    float4 v = *(const float4*)(hsrc + (size_t)(kb * 32 + kk) * BB + b0);
                    *(float4*)&sh[kk][b0] = v;
                }
                __syncthreads();
                #pragma unroll
                for (int kk = 0; kk < 32; kk++) {
                    ulonglong2 h2 = *(const ulonglong2*)&sh[kk][b0];     // b pairs
                    float4 w4 = *(const float4*)&sw[jl][kb * 32 + kk][0]; // broadcast
                    ull wi  = dup2(w4.x);
                    ull wfv = dup2(w4.y);
                    ull wg  = dup2(w4.z);
                    ull wov = dup2(w4.w);
                    ffma2(ai0, wi,  h2.x); ffma2(ai1, wi,  h2.y);
                    ffma2(af0, wfv, h2.x); ffma2(af1, wfv, h2.y);
                    ffma2(ag0, wg,  h2.x); ffma2(ag1, wg,  h2.y);
                    ffma2(ao0, wov, h2.x); ffma2(ao1, wov, h2.y);
                }
                __syncthreads();
            }
        }

        float ia[4], fa[4], ga[4], oa[4];
        unpack2(ia[0], ia[1], ai0); unpack2(ia[2], ia[3], ai1);
        unpack2(fa[0], fa[1], af0); unpack2(fa[2], fa[3], af1);
        unpack2(ga[0], ga[1], ag0); unpack2(ga[2], ga[3], ag1);
        unpack2(oa[0], oa[1], ao0); unpack2(oa[2], oa[3], ao1);

        const float* xr = g_xwT + (((size_t)dir * SS + t) * G4H + jg) * BB + b0;
        float4 xi = *(const float4*)(xr);
        float4 xf = *(const float4*)(xr + 256 * BB);
        float4 xg = *(const float4*)(xr + 512 * BB);
        float4 xo = *(const float4*)(xr + 768 * BB);
        float xiv[4] = {xi.x, xi.y, xi.z, xi.w};
        float xfv[4] = {xf.x, xf.y, xf.z, xf.w};
        float xgv[4] = {xg.x, xg.y, xg.z, xg.w};
        float xov[4] = {xo.x, xo.y, xo.z, xo.w};

        float hv[4];
        #pragma unroll
        for (int bb = 0; bb < 4; bb++) {
            float ig = sigmoidf_(ia[bb] + xiv[bb]);
            float fg = sigmoidf_(fa[bb] + xfv[bb]);
            float gg = tanhf(ga[bb] + xgv[bb]);
            float og = sigmoidf_(oa[bb] + xov[bb]);
            c[bb] = fg * c[bb] + ig * gg;
            hv[bb] = og * tanhf(c[bb]);
        }
        *(float4*)(g_hT + (((size_t)dir * SS + t) * HH + jg) * BB + b0) =
            make_float4(hv[0], hv[1], hv[2], hv[3]);

        if (st < SS - 1) {
            __threadfence();
            __syncthreads();
            if (tid == 0) {
                atomicAdd(&bar[st], 1);
                while (((volatile int*)bar)[st] < 64) { __nanosleep(64); }
            }
            __syncthreads();
        }
    }
}

// ---------------- K5: feats = lstm_out @ h2t_w^T + h2t_b ------------------
__global__ void k_feats(const float* __restrict__ h2t_w, const float* __restrict__ h2t_b)
{
    __shared__ float sw[TT * HIDD];      // 24 KB
    int t = blockIdx.x;
    int b = threadIdx.x;
    for (int i = b; i < TT * HIDD; i += 128) sw[i] = h2t_w[i];
    __syncthreads();

    float acc[TT];
    #pragma unroll
    for (int tg = 0; tg < TT; tg++) acc[tg] = h2t_b[tg];

    const float* hf = g_hT + ((size_t)(0 * SS + t) * HH) * BB + b;
    const float* hb = g_hT + ((size_t)(1 * SS + t) * HH) * BB + b;
    for (int j = 0; j < HH; j++) {
        float vf = hf[(size_t)j * BB];
        float vb = hb[(size_t)j * BB];
        #pragma unroll
        for (int tg = 0; tg < TT; tg++)
            acc[tg] += vf * sw[tg * HIDD + j] + vb * sw[tg * HIDD + HH + j];
    }
    float* dst = g_feats + (size_t)(t * BB + b) * TT;
    #pragma unroll
    for (int tg = 0; tg < TT; tg++) dst[tg] = acc[tg];
}

// ---------------- K6: Viterbi + backtrace ---------------------------------
// 16 blocks x (8 batch x 12 tags) threads.
__global__ void k_viterbi(const float* __restrict__ trans,
                          const int* __restrict__ mask,
                          float* __restrict__ out)
{
    __shared__ float str[TT * TT];
    __shared__ float alpha[8][TT];
    __shared__ float fin[8][TT];

    int tid = threadIdx.x;       // 0..95
    int bl = tid / TT;
    int nx = tid % TT;
    int b  = blockIdx.x * 8 + bl;

    for (int i = tid; i < TT * TT; i += 96) str[i] = trans[i];
    alpha[bl][nx] = (nx == TAG_START) ? 0.0f : -10000.0f;
    __syncthreads();

    for (int s = 0; s < SS; s++) {
        float f = g_feats[((size_t)(s * BB) + b) * TT + nx];
        float bestv = -3.4e38f; int bestp = 0;
        #pragma unroll
        for (int p = 0; p < TT; p++) {
            float v = (alpha[bl][p] + str[p * TT + nx]) + f;
            if (v > bestv) { bestv = v; bestp = p; }
        }
        g_bp[((size_t)(s * BB) + b) * TT + nx] = (unsigned char)bestp;
        int valid = mask[b * SS + s];
        float cur = alpha[bl][nx];
        __syncthreads();
        alpha[bl][nx] = valid ? bestv : cur;
        __syncthreads();
    }

    fin[bl][nx] = alpha[bl][nx] + str[TAG_STOP * TT + nx];
    __syncthreads();

    if (nx == 0) {
        float bv = fin[bl][0]; int bt = 0;
        #pragma unroll
        for (int p = 1; p < TT; p++)
            if (fin[bl][p] > bv) { bv = fin[bl][p]; bt = p; }
        out[b] = bv;

        int len = 0;
        for (int s = 0; s < SS; s++) len += mask[b * SS + s];

        int tag = bt;
        for (int s = SS - 1; s >= 0; s--) {
            if (s < len) {
                out[BB + b * SS + s] = (float)tag;
                tag = g_bp[((size_t)(s * BB) + b) * TT + tag];
            } else {
                out[BB + b * SS + s] = (float)TAG_PAD;
            }
        }
    }
}

// ---------------- launch ---------------------------------------------------
extern "C" void kernel_launch(void* const* d_in, const int* in_sizes, int n_in,
                              void* d_out, int out_size)
{
    (void)in_sizes; (void)n_in; (void)out_size;
    const int*   word_idxs  = (const int*)  d_in[0];
    const int*   char_idxs  = (const int*)  d_in[1];
    const int*   mask       = (const int*)  d_in[2];
    const float* word_table = (const float*)d_in[3];
    const float* char_table = (const float*)d_in[4];
    const float* conv_w     = (const float*)d_in[5];
    const float* conv_b     = (const float*)d_in[6];
    const float* w_ih_f     = (const float*)d_in[7];
    const float* w_hh_f     = (const float*)d_in[8];
    const float* b_ih_f     = (const float*)d_in[9];
    const float* b_hh_f     = (const float*)d_in[10];
    const float* w_ih_b     = (const float*)d_in[11];
    const float* w_hh_b     = (const float*)d_in[12];
    const float* b_ih_b     = (const float*)d_in[13];
    const float* b_hh_b     = (const float*)d_in[14];
    const float* h2t_w      = (const float*)d_in[15];
    const float* h2t_b      = (const float*)d_in[16];
    const float* trans      = (const float*)d_in[17];
    float* out = (float*)d_out;

    k_prep<<<(3 * CVV * CCC + 255) / 256, 256>>>(conv_w, char_table,
                                                 b_ih_f, b_hh_f, b_ih_b, b_hh_b);
    k_embed<<<BB * SS, 128>>>(word_idxs, char_idxs, word_table, conv_b);
    k_gemm<<<dim3(SS, 16), 256>>>(w_ih_f, w_ih_b);
    k_lstm<<<128, 128>>>(w_hh_f, w_hh_b);
    k_feats<<<SS, 128>>>(h2t_w, h2t_b);
    k_viterbi<<<16, 96>>>(trans, mask, out);
}

// round 17
// speedup vs baseline: 1.2222x; 1.1193x over previous
#include <cuda_runtime.h>
#include <cuda_bf16.h>
#include <cstdint>
#include <math.h>

// ---------------- problem constants ----------------
#define BB   128      // batch
#define SS   256      // seq len
#define WW   20       // chars per word
#define WVV  50000
#define CVV  100
#define WEE  300
#define CEE  50
#define CCC  100
#define HIDD 512
#define HH   256      // per-direction hidden
#define DINN 400      // WE + CC
#define TT   12
#define G4H  1024     // 4*H
#define TAG_START 9
#define TAG_STOP  10
#define TAG_PAD   11

// ---------------- device scratch (static, allocation-free) ----------------
__device__ float g_PT[3 * CVV * CCC];                    // projected char table [k][c][o]
__device__ float g_bias[2 * G4H];                        // b_ih + b_hh per dir
__device__ float g_emb[SS * BB * DINN];                  // [s][b][din]
__device__ float g_xwT[2u * SS * G4H * BB];              // [dir][t][col][b]
__device__ float g_hT [2u * SS * HH  * BB];              // [dir][t][j][b]
__device__ float g_feats[SS * BB * TT];                  // [s][b][tag]
__device__ unsigned char g_bp[SS * BB * TT];             // backpointers
__device__ int   g_bar[2 * SS];                          // per-step barriers

// ---------------- K1: precompute PT, fused biases, zero barriers ----------
__global__ void k_prep(const float* __restrict__ conv_w,
                       const float* __restrict__ char_table,
                       const float* __restrict__ bif, const float* __restrict__ bhf,
                       const float* __restrict__ bib, const float* __restrict__ bhb)
{
    int idx = blockIdx.x * blockDim.x + threadIdx.x;
    if (idx < 3 * CVV * CCC) {
        int o = idx % CCC;
        int c = (idx / CCC) % CVV;
        int k = idx / (CVV * CCC);
        float s = 0.f;
        #pragma unroll 10
        for (int e = 0; e < CEE; e++)
            s += conv_w[(o * CEE + e) * 3 + k] * char_table[c * CEE + e];
        g_PT[k * (CVV * CCC) + c * CCC + o] = s;
    }
    if (idx < G4H)            g_bias[idx]        = bif[idx]        + bhf[idx];
    else if (idx < 2 * G4H)   g_bias[idx]        = bib[idx - G4H]  + bhb[idx - G4H];
    if (idx < 2 * SS)         g_bar[idx] = 0;
}

// ---------------- K2: word gather + char conv/maxpool -> emb [s][b][din] ---
__global__ void k_embed(const int* __restrict__ widx,
                        const int* __restrict__ cidx,
                        const float* __restrict__ wt,
                        const float* __restrict__ cb)
{
    __shared__ int ch[WW];
    int bs  = blockIdx.x;           // 0..B*S-1
    int s   = bs >> 7;
    int b   = bs & 127;
    int tid = threadIdx.x;

    int w = widx[b * SS + s];
    float* dst = g_emb + (size_t)(s * BB + b) * DINN;
    for (int i = tid; i < WEE; i += 128)
        dst[i] = wt[(size_t)w * WEE + i];

    if (tid < WW) ch[tid] = cidx[((size_t)(b * SS + s)) * WW + tid];
    __syncthreads();

    if (tid < CCC) {
        int o = tid;
        float bias = cb[o];
        float m = -1e30f;
        const float* PT0 = g_PT;
        const float* PT1 = g_PT + CVV * CCC;
        const float* PT2 = g_PT + 2 * CVV * CCC;
        #pragma unroll
        for (int t = 0; t < WW; t++) {
            float v = bias + PT1[ch[t] * CCC + o];
            if (t > 0)      v += PT0[ch[t - 1] * CCC + o];
            if (t < WW - 1) v += PT2[ch[t + 1] * CCC + o];
            m = fmaxf(m, v);
        }
        dst[WEE + o] = fmaxf(m, 0.0f);
    }
}

// ---------------- K3: big input GEMM (R12 scalar version) -----------------
// C[dir][t][col][b] = sum_k W_ih[dir][col][k] * emb[t][b][k] + bias[dir][col]
// M = 2048 rows (dir x col), N = 32768 (t x b), K = 400.
__global__ void __launch_bounds__(256, 2)
k_gemm(const float* __restrict__ wf, const float* __restrict__ wb)
{
    __shared__ float sA[16][128];
    __shared__ float sB[16][128];

    int nb = blockIdx.x;            // t (one timestep per N-tile)
    int mb = blockIdx.y;            // M tile (128 rows)
    int tid = threadIdx.x;
    int tx = tid & 15, ty = tid >> 4;

    int dir = mb >> 3;
    int r0  = (mb & 7) * 128;
    const float* W    = dir ? wb : wf;
    const float* Brow = g_emb + (size_t)nb * BB * DINN;

    float acc[8][8];
    #pragma unroll
    for (int i = 0; i < 8; i++)
        #pragma unroll
        for (int j = 0; j < 8; j++) acc[i][j] = 0.f;

    for (int k0 = 0; k0 < DINN; k0 += 16) {
        #pragma unroll
        for (int it = 0; it < 2; it++) {
            int idx = tid + it * 256;
            int ml = idx >> 2, q = idx & 3;
            float4 va = *(const float4*)(W    + (size_t)(r0 + ml) * DINN + k0 + q * 4);
            sA[q*4+0][ml] = va.x; sA[q*4+1][ml] = va.y;
            sA[q*4+2][ml] = va.z; sA[q*4+3][ml] = va.w;
            float4 vb = *(const float4*)(Brow + (size_t)ml * DINN + k0 + q * 4);
            sB[q*4+0][ml] = vb.x; sB[q*4+1][ml] = vb.y;
            sB[q*4+2][ml] = vb.z; sB[q*4+3][ml] = vb.w;
        }
        __syncthreads();
        #pragma unroll
        for (int k = 0; k < 16; k++) {
            float4 a0 = *(const float4*)&sA[k][ty * 8];
            float4 a1 = *(const float4*)&sA[k][ty * 8 + 4];
            float4 b0 = *(const float4*)&sB[k][tx * 8];
            float4 b1 = *(const float4*)&sB[k][tx * 8 + 4];
            float av[8] = {a0.x,a0.y,a0.z,a0.w,a1.x,a1.y,a1.z,a1.w};
            float bv[8] = {b0.x,b0.y,b0.z,b0.w,b1.x,b1.y,b1.z,b1.w};
            #pragma unroll
            for (int i = 0; i < 8; i++)
                #pragma unroll
                for (int j = 0; j < 8; j++)
                    acc[i][j] += av[i] * bv[j];
        }
        __syncthreads();
    }

    int t = nb;
    #pragma unroll
    for (int i = 0; i < 8; i++) {
        int col = r0 + ty * 8 + i;                 // 0..1023
        float bi = g_bias[dir * G4H + col];
        float* orow = g_xwT + (((size_t)dir * SS + t) * G4H + col) * BB + tx * 8;
        float4 o0 = make_float4(acc[i][0]+bi, acc[i][1]+bi, acc[i][2]+bi, acc[i][3]+bi);
        float4 o1 = make_float4(acc[i][4]+bi, acc[i][5]+bi, acc[i][6]+bi, acc[i][7]+bi);
        *(float4*)(orow)     = o0;
        *(float4*)(orow + 4) = o1;
    }
}

// ---------------- K4: persistent BiLSTM recurrence ------------------------
// R12 structure + register-prefetch software pipeline for the h staging.
// 128 blocks (<=148 SMs, wave-1 co-resident). 64 blocks per direction.
// Block owns 4 h-indices (16 gate rows of W_hh resident in SMEM).
// Thread (lane, jl): 4 consecutive b, one j. c-state in registers.
__device__ __forceinline__ float sigmoidf_(float x) { return 1.0f / (1.0f + expf(-x)); }

__global__ void __launch_bounds__(128, 1)
k_lstm(const float* __restrict__ whh_f, const float* __restrict__ whh_b)
{
    __shared__ float sw[4][256][4];     // [jl][k][gate]  (16 KB)
    __shared__ float sh[32][132];       // [k-chunk][b]   (16.9 KB)

    int tid  = threadIdx.x;
    int dir  = blockIdx.x >> 6;
    int ib   = blockIdx.x & 63;
    int j0   = ib * 4;
    int lane = tid & 31;
    int jl   = tid >> 5;
    int b0   = lane * 4;
    int jg   = j0 + jl;

    const float* whh = dir ? whh_b : whh_f;
    for (int idx = tid; idx < 4096; idx += 128) {
        int jj  = idx >> 10;
        int rem = idx & 1023;
        int k   = rem >> 2;
        int g   = rem & 3;
        sw[jj][k][g] = whh[(size_t)((g << 8) + j0 + jj) * HH + k];
    }
    __syncthreads();

    float c[4] = {0.f, 0.f, 0.f, 0.f};
    int* bar = g_bar + dir * SS;

    for (int st = 0; st < SS; st++) {
        int t = dir ? (SS - 1 - st) : st;

        // hoist x-projection loads to step start (kb loop hides their latency)
        const float* xr = g_xwT + (((size_t)dir * SS + t) * G4H + jg) * BB + b0;
        float4 xi = *(const float4*)(xr);
        float4 xf = *(const float4*)(xr + 256 * BB);
        float4 xg = *(const float4*)(xr + 512 * BB);
        float4 xo = *(const float4*)(xr + 768 * BB);

        float acc[4][4];
        #pragma unroll
        for (int g = 0; g < 4; g++)
            #pragma unroll
            for (int bb = 0; bb < 4; bb++) acc[g][bb] = 0.f;

        if (st > 0) {
            int tp = dir ? (t + 1) : (t - 1);
            const float* hsrc = g_hT + ((size_t)(dir * SS + tp) * HH) * BB;

            // prefetch chunk 0 into registers
            float4 stg[8];
            #pragma unroll
            for (int ph = 0; ph < 8; ph++)
                stg[ph] = *(const float4*)(hsrc + (size_t)(ph * 4 + jl) * BB + b0);

            for (int kb = 0; kb < 8; kb++) {
                // commit staged chunk to SMEM
                #pragma unroll
                for (int ph = 0; ph < 8; ph++)
                    *(float4*)&sh[ph * 4 + jl][b0] = stg[ph];
                __syncthreads();

                // prefetch next chunk (latency hidden by compute below)
                if (kb < 7) {
                    #pragma unroll
                    for (int ph = 0; ph < 8; ph++)
                        stg[ph] = *(const float4*)(hsrc +
                            (size_t)((kb + 1) * 32 + ph * 4 + jl) * BB + b0);
                }

                #pragma unroll
                for (int kk = 0; kk < 32; kk++) {
                    float4 h4 = *(const float4*)&sh[kk][b0];
                    float4 w4 = *(const float4*)&sw[jl][kb * 32 + kk][0];
                    acc[0][0] += w4.x * h4.x; acc[0][1] += w4.x * h4.y;
                    acc[0][2] += w4.x * h4.z; acc[0][3] += w4.x * h4.w;
                    acc[1][0] += w4.y * h4.x; acc[1][1] += w4.y * h4.y;
                    acc[1][2] += w4.y * h4.z; acc[1][3] += w4.y * h4.w;
                    acc[2][0] += w4.z * h4.x; acc[2][1] += w4.z * h4.y;
                    acc[2][2] += w4.z * h4.z; acc[2][3] += w4.z * h4.w;
                    acc[3][0] += w4.w * h4.x; acc[3][1] += w4.w * h4.y;
                    acc[3][2] += w4.w * h4.z; acc[3][3] += w4.w * h4.w;
                }
                __syncthreads();
            }
        }

        float xiv[4] = {xi.x, xi.y, xi.z, xi.w};
        float xfv[4] = {xf.x, xf.y, xf.z, xf.w};
        float xgv[4] = {xg.x, xg.y, xg.z, xg.w};
        float xov[4] = {xo.x, xo.y, xo.z, xo.w};

        float hv[4];
        #pragma unroll
        for (int bb = 0; bb < 4; bb++) {
            float ig = sigmoidf_(acc[0][bb] + xiv[bb]);
            float fg = sigmoidf_(acc[1][bb] + xfv[bb]);
            float gg = tanhf(acc[2][bb] + xgv[bb]);
            float og = sigmoidf_(acc[3][bb] + xov[bb]);
            c[bb] = fg * c[bb] + ig * gg;
            hv[bb] = og * tanhf(c[bb]);
        }
        *(float4*)(g_hT + (((size_t)dir * SS + t) * HH + jg) * BB + b0) =
            make_float4(hv[0], hv[1], hv[2], hv[3]);

        if (st < SS - 1) {
            __threadfence();
            __syncthreads();
            if (tid == 0) {
                atomicAdd(&bar[st], 1);
                while (((volatile int*)bar)[st] < 64) { __nanosleep(64); }
            }
            __syncthreads();
        }
    }
}

// ---------------- K5: feats = lstm_out @ h2t_w^T + h2t_b ------------------
__global__ void k_feats(const float* __restrict__ h2t_w, const float* __restrict__ h2t_b)
{
    __shared__ float sw[TT * HIDD];      // 24 KB
    int t = blockIdx.x;
    int b = threadIdx.x;
    for (int i = b; i < TT * HIDD; i += 128) sw[i] = h2t_w[i];
    __syncthreads();

    float acc[TT];
    #pragma unroll
    for (int tg = 0; tg < TT; tg++) acc[tg] = h2t_b[tg];

    const float* hf = g_hT + ((size_t)(0 * SS + t) * HH) * BB + b;
    const float* hb = g_hT + ((size_t)(1 * SS + t) * HH) * BB + b;
    for (int j = 0; j < HH; j++) {
        float vf = hf[(size_t)j * BB];
        float vb = hb[(size_t)j * BB];
        #pragma unroll
        for (int tg = 0; tg < TT; tg++)
            acc[tg] += vf * sw[tg * HIDD + j] + vb * sw[tg * HIDD + HH + j];
    }
    float* dst = g_feats + (size_t)(t * BB + b) * TT;
    #pragma unroll
    for (int tg = 0; tg < TT; tg++) dst[tg] = acc[tg];
}

// ---------------- K6: Viterbi + backtrace ---------------------------------
// 16 blocks x (8 batch x 12 tags) threads.
__global__ void k_viterbi(const float* __restrict__ trans,
                          const int* __restrict__ mask,
                          float* __restrict__ out)
{
    __shared__ float str[TT * TT];
    __shared__ float alpha[8][TT];
    __shared__ float fin[8][TT];

    int tid = threadIdx.x;       // 0..95
    int bl = tid / TT;
    int nx = tid % TT;
    int b  = blockIdx.x * 8 + bl;

    for (int i = tid; i < TT * TT; i += 96) str[i] = trans[i];
    alpha[bl][nx] = (nx == TAG_START) ? 0.0f : -10000.0f;
    __syncthreads();

    for (int s = 0; s < SS; s++) {
        float f = g_feats[((size_t)(s * BB) + b) * TT + nx];
        float bestv = -3.4e38f; int bestp = 0;
        #pragma unroll
        for (int p = 0; p < TT; p++) {
            float v = (alpha[bl][p] + str[p * TT + nx]) + f;
            if (v > bestv) { bestv = v; bestp = p; }
        }
        g_bp[((size_t)(s * BB) + b) * TT + nx] = (unsigned char)bestp;
        int valid = mask[b * SS + s];
        float cur = alpha[bl][nx];
        __syncthreads();
        alpha[bl][nx] = valid ? bestv : cur;
        __syncthreads();
    }

    fin[bl][nx] = alpha[bl][nx] + str[TAG_STOP * TT + nx];
    __syncthreads();

    if (nx == 0) {
        float bv = fin[bl][0]; int bt = 0;
        #pragma unroll
        for (int p = 1; p < TT; p++)
            if (fin[bl][p] > bv) { bv = fin[bl][p]; bt = p; }
        out[b] = bv;

        int len = 0;
        for (int s = 0; s < SS; s++) len += mask[b * SS + s];

        int tag = bt;
        for (int s = SS - 1; s >= 0; s--) {
            if (s < len) {
                out[BB + b * SS + s] = (float)tag;
                tag = g_bp[((size_t)(s * BB) + b) * TT + tag];
            } else {
                out[BB + b * SS + s] = (float)TAG_PAD;
            }
        }
    }
}

// ---------------- launch ---------------------------------------------------
extern "C" void kernel_launch(void* const* d_in, const int* in_sizes, int n_in,
                              void* d_out, int out_size)
{
    (void)in_sizes; (void)n_in; (void)out_size;
    const int*   word_idxs  = (const int*)  d_in[0];
    const int*   char_idxs  = (const int*)  d_in[1];
    const int*   mask       = (const int*)  d_in[2];
    const float* word_table = (const float*)d_in[3];
    const float* char_table = (const float*)d_in[4];
    const float* conv_w     = (const float*)d_in[5];
    const float* conv_b     = (const float*)d_in[6];
    const float* w_ih_f     = (const float*)d_in[7];
    const float* w_hh_f     = (const float*)d_in[8];
    const float* b_ih_f     = (const float*)d_in[9];
    const float* b_hh_f     = (const float*)d_in[10];
    const float* w_ih_b     = (const float*)d_in[11];
    const float* w_hh_b     = (const float*)d_in[12];
    const float* b_ih_b     = (const float*)d_in[13];
    const float* b_hh_b     = (const float*)d_in[14];
    const float* h2t_w      = (const float*)d_in[15];
    const float* h2t_b      = (const float*)d_in[16];
    const float* trans      = (const float*)d_in[17];
    float* out = (float*)d_out;

    k_prep<<<(3 * CVV * CCC + 255) / 256, 256>>>(conv_w, char_table,
                                                 b_ih_f, b_hh_f, b_ih_b, b_hh_b);
    k_embed<<<BB * SS, 128>>>(word_idxs, char_idxs, word_table, conv_b);
    k_gemm<<<dim3(SS, 16), 256>>>(w_ih_f, w_ih_b);
    k_lstm<<<128, 128>>>(w_hh_f, w_hh_b);
    k_feats<<<SS, 128>>>(h2t_w, h2t_b);
    k_viterbi<<<16, 96>>>(trans, mask, out);
}